// round 1
// baseline (speedup 1.0000x reference)
#include <cuda_runtime.h>
#include <math.h>

// Problem constants
#define BB 4
#define TT 4096
#define DD 1024
#define HH 16
#define KP 256
#define DK 64
#define MROWS (BB*TT)          // 16384
#define BHN (BB*HH)            // 64

// ---------------------------------------------------------------------------
// Scratch (static device globals; no allocation allowed)
// ---------------------------------------------------------------------------
__device__ float g_Q[(size_t)MROWS * DD];     // 64 MB, layout [b,t,h,d] == row-major (M, D)
__device__ float g_K[(size_t)MROWS * DD];
__device__ float g_V[(size_t)MROWS * DD];
__device__ float g_ctx[(size_t)MROWS * DD];
__device__ float g_Kp[(size_t)BHN * KP * DK]; // 4 MB, [bh, k, d]
__device__ float g_Vp[(size_t)BHN * KP * DK];

// ---------------------------------------------------------------------------
// SGEMM: C[M,N] = A[M,K] * W[K,N] (+ bias), all row-major, fp32.
// BM=BN=128, BK=8, 256 threads, 8x8 per-thread microtile.
// grid = (N/128, M/128)
// ---------------------------------------------------------------------------
__global__ __launch_bounds__(256) void sgemm_kernel(
    const float* __restrict__ A, const float* __restrict__ W,
    float* __restrict__ C, const float* __restrict__ bias,
    int Kn, int Nn)
{
    __shared__ float As[8][128];   // transposed A tile: [k][m]
    __shared__ float Bs[8][128];   // [k][n]

    const int tid = threadIdx.x;
    const int row_c = (tid >> 4) << 3;   // 0..120 within tile (M)
    const int col_c = (tid & 15) << 3;   // 0..120 within tile (N)

    const float* Ab = A + (size_t)blockIdx.y * 128 * Kn;
    const float* Wb = W + (size_t)blockIdx.x * 128;

    const int arow = tid >> 1;           // 0..127
    const int acol = (tid & 1) << 2;     // 0 or 4
    const int brow = tid >> 5;           // 0..7
    const int bcol = (tid & 31) << 2;    // 0..124

    float acc[8][8];
#pragma unroll
    for (int i = 0; i < 8; i++)
#pragma unroll
        for (int j = 0; j < 8; j++) acc[i][j] = 0.f;

    for (int k0 = 0; k0 < Kn; k0 += 8) {
        float4 a4 = *(const float4*)(Ab + (size_t)arow * Kn + k0 + acol);
        As[acol + 0][arow] = a4.x;
        As[acol + 1][arow] = a4.y;
        As[acol + 2][arow] = a4.z;
        As[acol + 3][arow] = a4.w;
        *(float4*)&Bs[brow][bcol] =
            *(const float4*)(Wb + (size_t)(k0 + brow) * Nn + bcol);
        __syncthreads();

#pragma unroll
        for (int k = 0; k < 8; k++) {
            float ra[8], rb[8];
            *(float4*)&ra[0] = *(const float4*)&As[k][row_c];
            *(float4*)&ra[4] = *(const float4*)&As[k][row_c + 4];
            *(float4*)&rb[0] = *(const float4*)&Bs[k][col_c];
            *(float4*)&rb[4] = *(const float4*)&Bs[k][col_c + 4];
#pragma unroll
            for (int i = 0; i < 8; i++)
#pragma unroll
                for (int j = 0; j < 8; j++)
                    acc[i][j] = fmaf(ra[i], rb[j], acc[i][j]);
        }
        __syncthreads();
    }

    const int crow = blockIdx.y * 128 + row_c;
    const int ccol = blockIdx.x * 128 + col_c;
    float b0 = 0.f, b1 = 0.f, b2 = 0.f, b3 = 0.f, b4 = 0.f, b5 = 0.f, b6 = 0.f, b7 = 0.f;
    if (bias) {
        b0 = bias[ccol + 0]; b1 = bias[ccol + 1]; b2 = bias[ccol + 2]; b3 = bias[ccol + 3];
        b4 = bias[ccol + 4]; b5 = bias[ccol + 5]; b6 = bias[ccol + 6]; b7 = bias[ccol + 7];
    }
#pragma unroll
    for (int i = 0; i < 8; i++) {
        float4 v0, v1;
        v0.x = acc[i][0] + b0; v0.y = acc[i][1] + b1; v0.z = acc[i][2] + b2; v0.w = acc[i][3] + b3;
        v1.x = acc[i][4] + b4; v1.y = acc[i][5] + b5; v1.z = acc[i][6] + b6; v1.w = acc[i][7] + b7;
        *(float4*)(C + (size_t)(crow + i) * Nn + ccol)     = v0;
        *(float4*)(C + (size_t)(crow + i) * Nn + ccol + 4) = v1;
    }
}

// ---------------------------------------------------------------------------
// Low-rank projection (TN GEMM, batched over (b,h) and {K,V}):
//   Cp[bh][k][d] = sum_t E[t][k] * X[(b*T+t)*D + h*DK + d]
// grid = (KP/64, BHN, 2), 256 threads, 64x64 tile, 4x4 per-thread, t-tile 32.
// ---------------------------------------------------------------------------
__global__ __launch_bounds__(256) void proj_kernel(
    const float* __restrict__ Ek, const float* __restrict__ Ev,
    const float* __restrict__ Kb, const float* __restrict__ Vb,
    float* __restrict__ Kp, float* __restrict__ Vp)
{
    __shared__ float Es[32][68];   // [t][k]
    __shared__ float Xs[32][68];   // [t][d]

    const int z  = blockIdx.z;
    const float* E  = z ? Ev : Ek;
    const float* Xf = z ? Vb : Kb;
    float* Cp       = z ? Vp : Kp;

    const int k0 = blockIdx.x * 64;
    const int bh = blockIdx.y;
    const int b = bh >> 4, h = bh & 15;
    const float* X = Xf + (size_t)b * TT * DD + h * DK;
    float* C = Cp + (size_t)bh * KP * DK;

    const int tid = threadIdx.x;
    const int ty = tid >> 4;   // 0..15 -> k
    const int tx = tid & 15;   // 0..15 -> d

    float acc[4][4];
#pragma unroll
    for (int i = 0; i < 4; i++)
#pragma unroll
        for (int j = 0; j < 4; j++) acc[i][j] = 0.f;

    for (int t0 = 0; t0 < TT; t0 += 32) {
#pragma unroll
        for (int i = tid; i < 512; i += 256) {
            int r = i >> 4, c = (i & 15) << 2;
            *(float4*)&Es[r][c] = *(const float4*)(E + (size_t)(t0 + r) * KP + k0 + c);
            *(float4*)&Xs[r][c] = *(const float4*)(X + (size_t)(t0 + r) * DD + c);
        }
        __syncthreads();
#pragma unroll 8
        for (int t = 0; t < 32; t++) {
            float ra[4], rb[4];
#pragma unroll
            for (int i = 0; i < 4; i++) ra[i] = Es[t][ty * 4 + i];
#pragma unroll
            for (int j = 0; j < 4; j++) rb[j] = Xs[t][tx * 4 + j];
#pragma unroll
            for (int i = 0; i < 4; i++)
#pragma unroll
                for (int j = 0; j < 4; j++)
                    acc[i][j] = fmaf(ra[i], rb[j], acc[i][j]);
        }
        __syncthreads();
    }

#pragma unroll
    for (int i = 0; i < 4; i++) {
        float4 v; v.x = acc[i][0]; v.y = acc[i][1]; v.z = acc[i][2]; v.w = acc[i][3];
        *(float4*)(C + (size_t)(k0 + ty * 4 + i) * DK + tx * 4) = v;
    }
}

// ---------------------------------------------------------------------------
// Fused attention per (b,h) and 128-row t-tile:
//   scores = Q*Kp^T * 1/8 -> softmax(256) -> ctx = P * Vp
// grid = (T/128, BHN), 256 threads (8 warps, 16 rows/warp in 4x4-row groups).
// Dynamic smem: Kps[256][65] + Vps[256][65] + Qs[128][64] + Ps[8][1024]
// ---------------------------------------------------------------------------
#define ATTN_SMEM ((2*256*65 + 128*64 + 8*1024) * sizeof(float))   // 198656 B

__global__ __launch_bounds__(256) void attn_kernel(
    const float* __restrict__ Q, const float* __restrict__ Kp,
    const float* __restrict__ Vp, float* __restrict__ ctx)
{
    extern __shared__ float sm[];
    float* Kps = sm;                   // stride 65 per k-row
    float* Vps = Kps + 256 * 65;
    float* Qs  = Vps + 256 * 65;       // [128][64]
    float* Ps  = Qs  + 128 * 64;       // [warp][k*4 + r]

    const int bh = blockIdx.y;
    const int b = bh >> 4, h = bh & 15;
    const int t0 = blockIdx.x * 128;
    const int tid = threadIdx.x;

    const float* Kpb = Kp + (size_t)bh * KP * DK;
    const float* Vpb = Vp + (size_t)bh * KP * DK;

    // Load Kp/Vp (256x64) into padded smem
    for (int i = tid; i < (KP * DK) / 4; i += 256) {
        int r = i >> 4, c = (i & 15) << 2;
        float4 kv = *(const float4*)(Kpb + r * DK + c);
        Kps[r * 65 + c + 0] = kv.x; Kps[r * 65 + c + 1] = kv.y;
        Kps[r * 65 + c + 2] = kv.z; Kps[r * 65 + c + 3] = kv.w;
        float4 vv = *(const float4*)(Vpb + r * DK + c);
        Vps[r * 65 + c + 0] = vv.x; Vps[r * 65 + c + 1] = vv.y;
        Vps[r * 65 + c + 2] = vv.z; Vps[r * 65 + c + 3] = vv.w;
    }
    // Load Q tile (128x64)
    for (int i = tid; i < (128 * 64) / 4; i += 256) {
        int r = i >> 4, c = (i & 15) << 2;
        *(float4*)&Qs[r * 64 + c] =
            *(const float4*)(Q + (size_t)(b * TT + t0 + r) * DD + h * DK + c);
    }
    __syncthreads();

    const int warp = tid >> 5, lane = tid & 31;
    const float scale = 0.125f;  // 1/sqrt(64)
    float* Pw = Ps + warp * 1024;

    for (int rg = 0; rg < 4; rg++) {
        const int r0 = warp * 16 + rg * 4;

        // --- scores: s[r][j] over k = lane + 32*j ---
        float s[4][8];
#pragma unroll
        for (int r = 0; r < 4; r++)
#pragma unroll
            for (int j = 0; j < 8; j++) s[r][j] = 0.f;

#pragma unroll 4
        for (int d = 0; d < 64; d++) {
            float kv[8];
#pragma unroll
            for (int j = 0; j < 8; j++) kv[j] = Kps[(lane + 32 * j) * 65 + d];
#pragma unroll
            for (int r = 0; r < 4; r++) {
                float q = Qs[(r0 + r) * 64 + d];
#pragma unroll
                for (int j = 0; j < 8; j++) s[r][j] = fmaf(q, kv[j], s[r][j]);
            }
        }

        // --- softmax per row (warp-wide over 256) ---
#pragma unroll
        for (int r = 0; r < 4; r++) {
            float m = -1e30f;
#pragma unroll
            for (int j = 0; j < 8; j++) { s[r][j] *= scale; m = fmaxf(m, s[r][j]); }
#pragma unroll
            for (int off = 16; off; off >>= 1)
                m = fmaxf(m, __shfl_xor_sync(0xffffffffu, m, off));
            float sum = 0.f;
#pragma unroll
            for (int j = 0; j < 8; j++) { float e = __expf(s[r][j] - m); s[r][j] = e; sum += e; }
#pragma unroll
            for (int off = 16; off; off >>= 1)
                sum += __shfl_xor_sync(0xffffffffu, sum, off);
            float inv = __frcp_rn(sum);
#pragma unroll
            for (int j = 0; j < 8; j++)
                Pw[(lane + 32 * j) * 4 + r] = s[r][j] * inv;
        }
        __syncwarp();

        // --- ctx: acc[r][{d=lane, d=lane+32}] = sum_k P[r][k] * Vp[k][d] ---
        float acc00 = 0.f, acc01 = 0.f, acc10 = 0.f, acc11 = 0.f;
        float acc20 = 0.f, acc21 = 0.f, acc30 = 0.f, acc31 = 0.f;
        for (int k = 0; k < KP; k++) {
            float4 p = *(const float4*)&Pw[k * 4];   // broadcast
            float v0 = Vps[k * 65 + lane];
            float v1 = Vps[k * 65 + lane + 32];
            acc00 = fmaf(p.x, v0, acc00); acc01 = fmaf(p.x, v1, acc01);
            acc10 = fmaf(p.y, v0, acc10); acc11 = fmaf(p.y, v1, acc11);
            acc20 = fmaf(p.z, v0, acc20); acc21 = fmaf(p.z, v1, acc21);
            acc30 = fmaf(p.w, v0, acc30); acc31 = fmaf(p.w, v1, acc31);
        }
        {
            size_t base = (size_t)(b * TT + t0 + r0) * DD + h * DK;
            ctx[base + lane] = acc00;             ctx[base + lane + 32] = acc01;
            ctx[base + DD + lane] = acc10;        ctx[base + DD + lane + 32] = acc11;
            ctx[base + 2 * DD + lane] = acc20;    ctx[base + 2 * DD + lane + 32] = acc21;
            ctx[base + 3 * DD + lane] = acc30;    ctx[base + 3 * DD + lane + 32] = acc31;
        }
        __syncwarp();   // Pw reused next row-group
    }
}

// ---------------------------------------------------------------------------
// Launch
// ---------------------------------------------------------------------------
extern "C" void kernel_launch(void* const* d_in, const int* in_sizes, int n_in,
                              void* d_out, int out_size)
{
    const float* x  = (const float*)d_in[0];
    const float* Wq = (const float*)d_in[1];
    const float* Wk = (const float*)d_in[2];
    const float* Wv = (const float*)d_in[3];
    const float* Ek = (const float*)d_in[4];
    const float* Ev = (const float*)d_in[5];
    const float* Wo = (const float*)d_in[6];
    const float* bo = (const float*)d_in[7];
    float* out = (float*)d_out;

    float *Qb, *Kb, *Vb, *Ctx, *Kpp, *Vpp;
    cudaGetSymbolAddress((void**)&Qb,  g_Q);
    cudaGetSymbolAddress((void**)&Kb,  g_K);
    cudaGetSymbolAddress((void**)&Vb,  g_V);
    cudaGetSymbolAddress((void**)&Ctx, g_ctx);
    cudaGetSymbolAddress((void**)&Kpp, g_Kp);
    cudaGetSymbolAddress((void**)&Vpp, g_Vp);

    dim3 ggrid(DD / 128, MROWS / 128);
    // QKV projections
    sgemm_kernel<<<ggrid, 256>>>(x, Wq, Qb, nullptr, DD, DD);
    sgemm_kernel<<<ggrid, 256>>>(x, Wk, Kb, nullptr, DD, DD);
    sgemm_kernel<<<ggrid, 256>>>(x, Wv, Vb, nullptr, DD, DD);

    // Low-rank K/V projections
    proj_kernel<<<dim3(KP / 64, BHN, 2), 256>>>(Ek, Ev, Kb, Vb, Kpp, Vpp);

    // Fused attention
    cudaFuncSetAttribute(attn_kernel, cudaFuncAttributeMaxDynamicSharedMemorySize,
                         (int)ATTN_SMEM);
    attn_kernel<<<dim3(TT / 128, BHN), 256, ATTN_SMEM>>>(Qb, Kpp, Vpp, Ctx);

    // Output projection + bias
    sgemm_kernel<<<ggrid, 256>>>(Ctx, Wo, out, bo, DD, DD);
}

// round 3
// speedup vs baseline: 1.6177x; 1.6177x over previous
#include <cuda_runtime.h>
#include <cuda_bf16.h>
#include <cstdint>
#include <math.h>

// Problem constants
#define BB 4
#define TT 4096
#define DD 1024
#define HH 16
#define KP 256
#define DK 64
#define MROWS (BB*TT)          // 16384
#define BHN (BB*HH)            // 64

// ---------------------------------------------------------------------------
// Scratch (static device globals; no allocation allowed)
// ---------------------------------------------------------------------------
__device__ float g_Q[(size_t)MROWS * DD];
__device__ float g_K[(size_t)MROWS * DD];
__device__ float g_V[(size_t)MROWS * DD];
__device__ float g_ctx[(size_t)MROWS * DD];
__device__ float g_Kp[(size_t)BHN * KP * DK];
__device__ float g_Vp[(size_t)BHN * KP * DK];
// bf16 split operands (A buffer reused for x and ctx)
__device__ __nv_bfloat16 g_Ah[(size_t)MROWS * DD];
__device__ __nv_bfloat16 g_Al[(size_t)MROWS * DD];
__device__ __nv_bfloat16 g_Wh[4][(size_t)DD * DD];   // transposed [N][K]
__device__ __nv_bfloat16 g_Wl[4][(size_t)DD * DD];

// ---------------------------------------------------------------------------
// Helpers
// ---------------------------------------------------------------------------
__device__ __forceinline__ uint32_t smem_u32(const void* p) {
    uint32_t a;
    asm("{ .reg .u64 t; cvta.to.shared.u64 t, %1; cvt.u32.u64 %0, t; }" : "=r"(a) : "l"(p));
    return a;
}

#define CP_ASYNC16(dst, src) \
    asm volatile("cp.async.cg.shared.global [%0], [%1], 16;" :: "r"(dst), "l"(src))
#define CP_COMMIT() asm volatile("cp.async.commit_group;")
#define CP_WAIT0()  asm volatile("cp.async.wait_group 0;" ::: "memory")

#define LDMATRIX_X4(r0, r1, r2, r3, addr) \
    asm volatile("ldmatrix.sync.aligned.m8n8.x4.shared.b16 {%0,%1,%2,%3}, [%4];" \
        : "=r"(r0), "=r"(r1), "=r"(r2), "=r"(r3) : "r"(addr))

#define MMA_BF16(d, a, b0_, b1_) \
    asm volatile("mma.sync.aligned.m16n8k16.row.col.f32.bf16.bf16.f32 " \
        "{%0,%1,%2,%3},{%4,%5,%6,%7},{%8,%9},{%0,%1,%2,%3};" \
        : "+f"((d)[0]), "+f"((d)[1]), "+f"((d)[2]), "+f"((d)[3]) \
        : "r"((a)[0]), "r"((a)[1]), "r"((a)[2]), "r"((a)[3]), "r"(b0_), "r"(b1_))

// ---------------------------------------------------------------------------
// Split fp32 -> bf16 hi/lo (vectorized x4)
// ---------------------------------------------------------------------------
__global__ __launch_bounds__(256) void split_kernel(
    const float* __restrict__ src, __nv_bfloat16* __restrict__ hi,
    __nv_bfloat16* __restrict__ lo, int n4)
{
    __nv_bfloat162* hi2 = (__nv_bfloat162*)hi;
    __nv_bfloat162* lo2 = (__nv_bfloat162*)lo;
    int stride = gridDim.x * blockDim.x;
    for (int i = blockIdx.x * blockDim.x + threadIdx.x; i < n4; i += stride) {
        float4 v = ((const float4*)src)[i];
        __nv_bfloat16 hx = __float2bfloat16(v.x), hy = __float2bfloat16(v.y);
        __nv_bfloat16 hz = __float2bfloat16(v.z), hw = __float2bfloat16(v.w);
        hi2[2 * i + 0] = __halves2bfloat162(hx, hy);
        hi2[2 * i + 1] = __halves2bfloat162(hz, hw);
        lo2[2 * i + 0] = __halves2bfloat162(
            __float2bfloat16(v.x - __bfloat162float(hx)),
            __float2bfloat16(v.y - __bfloat162float(hy)));
        lo2[2 * i + 1] = __halves2bfloat162(
            __float2bfloat16(v.z - __bfloat162float(hz)),
            __float2bfloat16(v.w - __bfloat162float(hw)));
    }
}

// Transpose + split weights: W[K,N] fp32 -> Wt_hi/lo[N,K] bf16
__global__ __launch_bounds__(256) void wsplit_kernel(
    const float* __restrict__ W, __nv_bfloat16* __restrict__ hiT,
    __nv_bfloat16* __restrict__ loT)
{
    __shared__ float t[32][33];
    const int n0 = blockIdx.x * 32, k0 = blockIdx.y * 32;
    const int tx = threadIdx.x & 31, ty = threadIdx.x >> 5;
#pragma unroll
    for (int r = 0; r < 32; r += 8)
        t[ty + r][tx] = W[(size_t)(k0 + ty + r) * DD + n0 + tx];
    __syncthreads();
#pragma unroll
    for (int r = 0; r < 32; r += 8) {
        float v = t[tx][ty + r];               // element W[k0+tx][n0+ty+r]
        __nv_bfloat16 h = __float2bfloat16(v);
        size_t o = (size_t)(n0 + ty + r) * DD + k0 + tx;
        hiT[o] = h;
        loT[o] = __float2bfloat16(v - __bfloat162float(h));
    }
}

// ---------------------------------------------------------------------------
// mma.sync bf16-split GEMM: C[M,N] = (Ah+Al)[M,K] * (Bh+Bl)^T  (+bias)
//   acc += Ah*Bh + Al*Bh + Ah*Bl  (fp32 accumulators, registers)
// Block 128x128, K-chunk 32, 8 warps (warp tile 32x64), cp.async double buffer.
// A tiles [128][32] bf16, rows padded to 80B (conflict-free ldmatrix).
// grid = (N/128, M/128), 256 threads.
// ---------------------------------------------------------------------------
#define TILE_B   10240                 // 128 rows * 80 B
#define STAGE_B  (4 * TILE_B)          // AH, AL, BH, BL
#define TC_SMEM  (2 * STAGE_B)         // 81920

__global__ __launch_bounds__(256) void tc_gemm(
    const __nv_bfloat16* __restrict__ Ah, const __nv_bfloat16* __restrict__ Al,
    const __nv_bfloat16* __restrict__ Bh, const __nv_bfloat16* __restrict__ Bl,
    float* __restrict__ C, const float* __restrict__ bias, int Kn, int Nn)
{
    extern __shared__ char smem[];
    const uint32_t sbase = smem_u32(smem);
    const int tid = threadIdx.x, wid = tid >> 5, lane = tid & 31;
    const int warp_m = wid >> 1, warp_n = wid & 1;
    const int m0 = blockIdx.y * 128, n0 = blockIdx.x * 128;

    float acc[2][8][4];
#pragma unroll
    for (int mt = 0; mt < 2; mt++)
#pragma unroll
        for (int nt = 0; nt < 8; nt++)
#pragma unroll
            for (int q = 0; q < 4; q++) acc[mt][nt][q] = 0.f;

    // per-lane ldmatrix row offset within a tile
    const uint32_t lofs = ((((lane >> 3) & 1) * 8 + (lane & 7)) * 80u) + ((lane >> 4) * 16u);

    const int ld_row0 = tid >> 2;        // 0..63
    const int ld_col  = tid & 3;         // 16B chunk (k) 0..3

    // ---- pipeline ----
    const int NC = Kn >> 5;              // K chunks of 32
#define LOAD_STAGE(s, k0v) do {                                                   \
        const uint32_t stg = sbase + (uint32_t)(s) * STAGE_B;                     \
        _Pragma("unroll")                                                         \
        for (int i = 0; i < 8; i++) {                                             \
            const int tile = i >> 1;                                              \
            const int row = (i & 1) * 64 + ld_row0;                               \
            const uint32_t dst = stg + tile * TILE_B + row * 80 + ld_col * 16;    \
            const __nv_bfloat16* sp =                                             \
                (tile == 0 ? Ah : tile == 1 ? Al : tile == 2 ? Bh : Bl);          \
            const int grow = (tile < 2 ? m0 : n0) + row;                          \
            const __nv_bfloat16* src = sp + (size_t)grow * Kn + (k0v) + ld_col*8; \
            CP_ASYNC16(dst, src);                                                 \
        }                                                                         \
        CP_COMMIT();                                                              \
    } while (0)

    LOAD_STAGE(0, 0);

    for (int c = 0; c < NC; c++) {
        CP_WAIT0();
        __syncthreads();
        if (c + 1 < NC) LOAD_STAGE((c + 1) & 1, (c + 1) << 5);

        const uint32_t stg = sbase + (uint32_t)(c & 1) * STAGE_B;
        const uint32_t a_base = stg + (warp_m * 32) * 80 + lofs;
        const uint32_t b_base = stg + 2 * TILE_B + (warp_n * 64) * 80 + lofs;

#pragma unroll
        for (int ks = 0; ks < 2; ks++) {
            uint32_t ah[2][4], al[2][4], b[4][4];
            // A fragments (hi then lo)
#pragma unroll
            for (int mt = 0; mt < 2; mt++) {
                LDMATRIX_X4(ah[mt][0], ah[mt][1], ah[mt][2], ah[mt][3],
                            a_base + mt * (16 * 80) + ks * 32);
                LDMATRIX_X4(al[mt][0], al[mt][1], al[mt][2], al[mt][3],
                            a_base + TILE_B + mt * (16 * 80) + ks * 32);
            }
            // B hi fragments
#pragma unroll
            for (int nq = 0; nq < 4; nq++)
                LDMATRIX_X4(b[nq][0], b[nq][1], b[nq][2], b[nq][3],
                            b_base + nq * (16 * 80) + ks * 32);
            // acc += Ah*Bh + Al*Bh
#pragma unroll
            for (int mt = 0; mt < 2; mt++)
#pragma unroll
                for (int nt = 0; nt < 8; nt++) {
                    const int nq = nt >> 1, sel = nt & 1;
                    MMA_BF16(acc[mt][nt], ah[mt], b[nq][sel], b[nq][sel + 2]);
                    MMA_BF16(acc[mt][nt], al[mt], b[nq][sel], b[nq][sel + 2]);
                }
            // B lo fragments (reuse regs)
#pragma unroll
            for (int nq = 0; nq < 4; nq++)
                LDMATRIX_X4(b[nq][0], b[nq][1], b[nq][2], b[nq][3],
                            b_base + TILE_B + nq * (16 * 80) + ks * 32);
            // acc += Ah*Bl
#pragma unroll
            for (int mt = 0; mt < 2; mt++)
#pragma unroll
                for (int nt = 0; nt < 8; nt++) {
                    const int nq = nt >> 1, sel = nt & 1;
                    MMA_BF16(acc[mt][nt], ah[mt], b[nq][sel], b[nq][sel + 2]);
                }
        }
        __syncthreads();
    }
#undef LOAD_STAGE

    // ---- epilogue ----
    const int g = lane >> 2, tig = lane & 3;
#pragma unroll
    for (int mt = 0; mt < 2; mt++) {
        const int row0 = m0 + warp_m * 32 + mt * 16 + g;
#pragma unroll
        for (int nt = 0; nt < 8; nt++) {
            const int col = n0 + warp_n * 64 + nt * 8 + 2 * tig;
            float bx = 0.f, by = 0.f;
            if (bias) { bx = bias[col]; by = bias[col + 1]; }
            float2 v0 = make_float2(acc[mt][nt][0] + bx, acc[mt][nt][1] + by);
            float2 v1 = make_float2(acc[mt][nt][2] + bx, acc[mt][nt][3] + by);
            *(float2*)(C + (size_t)row0 * Nn + col) = v0;
            *(float2*)(C + (size_t)(row0 + 8) * Nn + col) = v1;
        }
    }
}

// ---------------------------------------------------------------------------
// Low-rank projection (float4 LDS reads)
// ---------------------------------------------------------------------------
__global__ __launch_bounds__(256) void proj_kernel(
    const float* __restrict__ Ek, const float* __restrict__ Ev,
    const float* __restrict__ Kb, const float* __restrict__ Vb,
    float* __restrict__ Kp, float* __restrict__ Vp)
{
    __shared__ float Es[32][68];
    __shared__ float Xs[32][68];

    const int z  = blockIdx.z;
    const float* E  = z ? Ev : Ek;
    const float* Xf = z ? Vb : Kb;
    float* Cp       = z ? Vp : Kp;

    const int k0 = blockIdx.x * 64;
    const int bh = blockIdx.y;
    const int b = bh >> 4, h = bh & 15;
    const float* X = Xf + (size_t)b * TT * DD + h * DK;
    float* C = Cp + (size_t)bh * KP * DK;

    const int tid = threadIdx.x;
    const int ty = tid >> 4;
    const int tx = tid & 15;

    float acc[4][4];
#pragma unroll
    for (int i = 0; i < 4; i++)
#pragma unroll
        for (int j = 0; j < 4; j++) acc[i][j] = 0.f;

    for (int t0 = 0; t0 < TT; t0 += 32) {
#pragma unroll
        for (int i = tid; i < 512; i += 256) {
            int r = i >> 4, c = (i & 15) << 2;
            *(float4*)&Es[r][c] = *(const float4*)(E + (size_t)(t0 + r) * KP + k0 + c);
            *(float4*)&Xs[r][c] = *(const float4*)(X + (size_t)(t0 + r) * DD + c);
        }
        __syncthreads();
#pragma unroll 8
        for (int t = 0; t < 32; t++) {
            float4 ra = *(const float4*)&Es[t][ty * 4];
            float4 rb = *(const float4*)&Xs[t][tx * 4];
            float ar[4] = {ra.x, ra.y, ra.z, ra.w};
            float br[4] = {rb.x, rb.y, rb.z, rb.w};
#pragma unroll
            for (int i = 0; i < 4; i++)
#pragma unroll
                for (int j = 0; j < 4; j++)
                    acc[i][j] = fmaf(ar[i], br[j], acc[i][j]);
        }
        __syncthreads();
    }

#pragma unroll
    for (int i = 0; i < 4; i++) {
        float4 v; v.x = acc[i][0]; v.y = acc[i][1]; v.z = acc[i][2]; v.w = acc[i][3];
        *(float4*)(C + (size_t)(k0 + ty * 4 + i) * DK + tx * 4) = v;
    }
}

// ---------------------------------------------------------------------------
// Fused attention (unchanged)
// ---------------------------------------------------------------------------
#define ATTN_SMEM ((2*256*65 + 128*64 + 8*1024) * sizeof(float))

__global__ __launch_bounds__(256) void attn_kernel(
    const float* __restrict__ Q, const float* __restrict__ Kp,
    const float* __restrict__ Vp, float* __restrict__ ctx)
{
    extern __shared__ float sm[];
    float* Kps = sm;
    float* Vps = Kps + 256 * 65;
    float* Qs  = Vps + 256 * 65;
    float* Ps  = Qs  + 128 * 64;

    const int bh = blockIdx.y;
    const int b = bh >> 4, h = bh & 15;
    const int t0 = blockIdx.x * 128;
    const int tid = threadIdx.x;

    const float* Kpb = Kp + (size_t)bh * KP * DK;
    const float* Vpb = Vp + (size_t)bh * KP * DK;

    for (int i = tid; i < (KP * DK) / 4; i += 256) {
        int r = i >> 4, c = (i & 15) << 2;
        float4 kv = *(const float4*)(Kpb + r * DK + c);
        Kps[r * 65 + c + 0] = kv.x; Kps[r * 65 + c + 1] = kv.y;
        Kps[r * 65 + c + 2] = kv.z; Kps[r * 65 + c + 3] = kv.w;
        float4 vv = *(const float4*)(Vpb + r * DK + c);
        Vps[r * 65 + c + 0] = vv.x; Vps[r * 65 + c + 1] = vv.y;
        Vps[r * 65 + c + 2] = vv.z; Vps[r * 65 + c + 3] = vv.w;
    }
    for (int i = tid; i < (128 * 64) / 4; i += 256) {
        int r = i >> 4, c = (i & 15) << 2;
        *(float4*)&Qs[r * 64 + c] =
            *(const float4*)(Q + (size_t)(b * TT + t0 + r) * DD + h * DK + c);
    }
    __syncthreads();

    const int warp = tid >> 5, lane = tid & 31;
    const float scale = 0.125f;
    float* Pw = Ps + warp * 1024;

    for (int rg = 0; rg < 4; rg++) {
        const int r0 = warp * 16 + rg * 4;

        float s[4][8];
#pragma unroll
        for (int r = 0; r < 4; r++)
#pragma unroll
            for (int j = 0; j < 8; j++) s[r][j] = 0.f;

#pragma unroll 4
        for (int d = 0; d < 64; d++) {
            float kv[8];
#pragma unroll
            for (int j = 0; j < 8; j++) kv[j] = Kps[(lane + 32 * j) * 65 + d];
#pragma unroll
            for (int r = 0; r < 4; r++) {
                float q = Qs[(r0 + r) * 64 + d];
#pragma unroll
                for (int j = 0; j < 8; j++) s[r][j] = fmaf(q, kv[j], s[r][j]);
            }
        }

#pragma unroll
        for (int r = 0; r < 4; r++) {
            float m = -1e30f;
#pragma unroll
            for (int j = 0; j < 8; j++) { s[r][j] *= scale; m = fmaxf(m, s[r][j]); }
#pragma unroll
            for (int off = 16; off; off >>= 1)
                m = fmaxf(m, __shfl_xor_sync(0xffffffffu, m, off));
            float sum = 0.f;
#pragma unroll
            for (int j = 0; j < 8; j++) { float e = __expf(s[r][j] - m); s[r][j] = e; sum += e; }
#pragma unroll
            for (int off = 16; off; off >>= 1)
                sum += __shfl_xor_sync(0xffffffffu, sum, off);
            float inv = __frcp_rn(sum);
#pragma unroll
            for (int j = 0; j < 8; j++)
                Pw[(lane + 32 * j) * 4 + r] = s[r][j] * inv;
        }
        __syncwarp();

        float acc00 = 0.f, acc01 = 0.f, acc10 = 0.f, acc11 = 0.f;
        float acc20 = 0.f, acc21 = 0.f, acc30 = 0.f, acc31 = 0.f;
        for (int k = 0; k < KP; k++) {
            float4 p = *(const float4*)&Pw[k * 4];
            float v0 = Vps[k * 65 + lane];
            float v1 = Vps[k * 65 + lane + 32];
            acc00 = fmaf(p.x, v0, acc00); acc01 = fmaf(p.x, v1, acc01);
            acc10 = fmaf(p.y, v0, acc10); acc11 = fmaf(p.y, v1, acc11);
            acc20 = fmaf(p.z, v0, acc20); acc21 = fmaf(p.z, v1, acc21);
            acc30 = fmaf(p.w, v0, acc30); acc31 = fmaf(p.w, v1, acc31);
        }
        {
            size_t base = (size_t)(b * TT + t0 + r0) * DD + h * DK;
            ctx[base + lane] = acc00;             ctx[base + lane + 32] = acc01;
            ctx[base + DD + lane] = acc10;        ctx[base + DD + lane + 32] = acc11;
            ctx[base + 2 * DD + lane] = acc20;    ctx[base + 2 * DD + lane + 32] = acc21;
            ctx[base + 3 * DD + lane] = acc30;    ctx[base + 3 * DD + lane + 32] = acc31;
        }
        __syncwarp();
    }
}

// ---------------------------------------------------------------------------
// Launch
// ---------------------------------------------------------------------------
extern "C" void kernel_launch(void* const* d_in, const int* in_sizes, int n_in,
                              void* d_out, int out_size)
{
    const float* x  = (const float*)d_in[0];
    const float* Wq = (const float*)d_in[1];
    const float* Wk = (const float*)d_in[2];
    const float* Wv = (const float*)d_in[3];
    const float* Ek = (const float*)d_in[4];
    const float* Ev = (const float*)d_in[5];
    const float* Wo = (const float*)d_in[6];
    const float* bo = (const float*)d_in[7];
    float* out = (float*)d_out;

    float *Qb, *Kb, *Vb, *Ctx, *Kpp, *Vpp;
    __nv_bfloat16 *Ahp, *Alp, *Whp, *Wlp;
    cudaGetSymbolAddress((void**)&Qb,  g_Q);
    cudaGetSymbolAddress((void**)&Kb,  g_K);
    cudaGetSymbolAddress((void**)&Vb,  g_V);
    cudaGetSymbolAddress((void**)&Ctx, g_ctx);
    cudaGetSymbolAddress((void**)&Kpp, g_Kp);
    cudaGetSymbolAddress((void**)&Vpp, g_Vp);
    cudaGetSymbolAddress((void**)&Ahp, g_Ah);
    cudaGetSymbolAddress((void**)&Alp, g_Al);
    cudaGetSymbolAddress((void**)&Whp, g_Wh);
    cudaGetSymbolAddress((void**)&Wlp, g_Wl);

    const size_t WSZ = (size_t)DD * DD;
    __nv_bfloat16* Wqh = Whp + 0 * WSZ; __nv_bfloat16* Wql = Wlp + 0 * WSZ;
    __nv_bfloat16* Wkh = Whp + 1 * WSZ; __nv_bfloat16* Wkl = Wlp + 1 * WSZ;
    __nv_bfloat16* Wvh = Whp + 2 * WSZ; __nv_bfloat16* Wvl = Wlp + 2 * WSZ;
    __nv_bfloat16* Woh = Whp + 3 * WSZ; __nv_bfloat16* Wol = Wlp + 3 * WSZ;

    cudaFuncSetAttribute(tc_gemm, cudaFuncAttributeMaxDynamicSharedMemorySize, TC_SMEM);
    cudaFuncSetAttribute(attn_kernel, cudaFuncAttributeMaxDynamicSharedMemorySize, (int)ATTN_SMEM);

    // 1) split x -> bf16 hi/lo
    split_kernel<<<2048, 256>>>(x, Ahp, Alp, MROWS * DD / 4);
    // 2) transpose+split weights
    dim3 wgrid(DD / 32, DD / 32);
    wsplit_kernel<<<wgrid, 256>>>(Wq, Wqh, Wql);
    wsplit_kernel<<<wgrid, 256>>>(Wk, Wkh, Wkl);
    wsplit_kernel<<<wgrid, 256>>>(Wv, Wvh, Wvl);
    wsplit_kernel<<<wgrid, 256>>>(Wo, Woh, Wol);

    // 3) QKV projections on tensor cores (mma.sync bf16 split)
    dim3 ggrid(DD / 128, MROWS / 128);
    tc_gemm<<<ggrid, 256, TC_SMEM>>>(Ahp, Alp, Wqh, Wql, Qb, nullptr, DD, DD);
    tc_gemm<<<ggrid, 256, TC_SMEM>>>(Ahp, Alp, Wkh, Wkl, Kb, nullptr, DD, DD);
    tc_gemm<<<ggrid, 256, TC_SMEM>>>(Ahp, Alp, Wvh, Wvl, Vb, nullptr, DD, DD);

    // 4) low-rank K/V projections (fp32)
    proj_kernel<<<dim3(KP / 64, BHN, 2), 256>>>(Ek, Ev, Kb, Vb, Kpp, Vpp);

    // 5) fused attention (fp32)
    attn_kernel<<<dim3(TT / 128, BHN), 256, ATTN_SMEM>>>(Qb, Kpp, Vpp, Ctx);

    // 6) split ctx, output projection + bias on tensor cores
    split_kernel<<<2048, 256>>>(Ctx, Ahp, Alp, MROWS * DD / 4);
    tc_gemm<<<ggrid, 256, TC_SMEM>>>(Ahp, Alp, Woh, Wol, out, bo, DD, DD);
}

// round 4
// speedup vs baseline: 2.2308x; 1.3789x over previous
#include <cuda_runtime.h>
#include <cuda_bf16.h>
#include <cstdint>
#include <math.h>

// Problem constants
#define BB 4
#define TT 4096
#define DD 1024
#define HH 16
#define KP 256
#define DK 64
#define MROWS (BB*TT)          // 16384
#define BHN (BB*HH)            // 64

typedef __nv_bfloat16 bf16;
typedef __nv_bfloat162 bf162;

// ---------------------------------------------------------------------------
// Scratch (static device globals; no allocation allowed)
// ---------------------------------------------------------------------------
__device__ bf16 g_Ah[(size_t)MROWS * DD];      // x split, later ctx split
__device__ bf16 g_Al[(size_t)MROWS * DD];
__device__ bf16 g_Qh[(size_t)MROWS * DD];
__device__ bf16 g_Ql[(size_t)MROWS * DD];
__device__ bf16 g_Kh[(size_t)MROWS * DD];
__device__ bf16 g_Kl[(size_t)MROWS * DD];
__device__ bf16 g_Vh[(size_t)MROWS * DD];
__device__ bf16 g_Vl[(size_t)MROWS * DD];
__device__ bf16 g_Wh[4][(size_t)DD * DD];      // transposed [N][K]
__device__ bf16 g_Wl[4][(size_t)DD * DD];
__device__ bf16 g_Eth[(size_t)2 * KP * TT];    // E^T split [z][kp][t]
__device__ bf16 g_Etl[(size_t)2 * KP * TT];
__device__ bf16 g_Kph[(size_t)BHN * KP * DK];
__device__ bf16 g_Kpl[(size_t)BHN * KP * DK];
__device__ bf16 g_Vph[(size_t)BHN * KP * DK];
__device__ bf16 g_Vpl[(size_t)BHN * KP * DK];

// ---------------------------------------------------------------------------
// Helpers
// ---------------------------------------------------------------------------
__device__ __forceinline__ uint32_t smem_u32(const void* p) {
    uint32_t a;
    asm("{ .reg .u64 t; cvta.to.shared.u64 t, %1; cvt.u32.u64 %0, t; }" : "=r"(a) : "l"(p));
    return a;
}

#define CP_ASYNC16(dst, src) \
    asm volatile("cp.async.cg.shared.global [%0], [%1], 16;" :: "r"(dst), "l"(src))
#define CP_COMMIT() asm volatile("cp.async.commit_group;")
#define CP_WAIT0()  asm volatile("cp.async.wait_group 0;" ::: "memory")

#define LDMATRIX_X4(r0, r1, r2, r3, addr) \
    asm volatile("ldmatrix.sync.aligned.m8n8.x4.shared.b16 {%0,%1,%2,%3}, [%4];" \
        : "=r"(r0), "=r"(r1), "=r"(r2), "=r"(r3) : "r"(addr))
#define LDMATRIX_X4_T(r0, r1, r2, r3, addr) \
    asm volatile("ldmatrix.sync.aligned.m8n8.x4.trans.shared.b16 {%0,%1,%2,%3}, [%4];" \
        : "=r"(r0), "=r"(r1), "=r"(r2), "=r"(r3) : "r"(addr))

#define MMA_BF16(d, a, b0_, b1_) \
    asm volatile("mma.sync.aligned.m16n8k16.row.col.f32.bf16.bf16.f32 " \
        "{%0,%1,%2,%3},{%4,%5,%6,%7},{%8,%9},{%0,%1,%2,%3};" \
        : "+f"((d)[0]), "+f"((d)[1]), "+f"((d)[2]), "+f"((d)[3]) \
        : "r"((a)[0]), "r"((a)[1]), "r"((a)[2]), "r"((a)[3]), "r"(b0_), "r"(b1_))

__device__ __forceinline__ uint32_t pack_bf16(float a, float b) {
    bf162 t = __floats2bfloat162_rn(a, b);
    return *(uint32_t*)&t;
}
__device__ __forceinline__ void split2(float a, float b, uint32_t& hi, uint32_t& lo) {
    bf16 ha = __float2bfloat16(a), hb = __float2bfloat16(b);
    hi = pack_bf16(a, b);  // rn pack of hi parts
    // recompute exact hi parts for residual
    bf162 hv = *(bf162*)&hi;
    lo = pack_bf16(a - __bfloat162float(hv.x), b - __bfloat162float(hv.y));
    (void)ha; (void)hb;
}

// ---------------------------------------------------------------------------
// Split fp32 -> bf16 hi/lo (vectorized x4)
// ---------------------------------------------------------------------------
__global__ __launch_bounds__(256) void split_kernel(
    const float* __restrict__ src, bf16* __restrict__ hi,
    bf16* __restrict__ lo, int n4)
{
    bf162* hi2 = (bf162*)hi;
    bf162* lo2 = (bf162*)lo;
    int stride = gridDim.x * blockDim.x;
    for (int i = blockIdx.x * blockDim.x + threadIdx.x; i < n4; i += stride) {
        float4 v = ((const float4*)src)[i];
        bf16 hx = __float2bfloat16(v.x), hy = __float2bfloat16(v.y);
        bf16 hz = __float2bfloat16(v.z), hw = __float2bfloat16(v.w);
        hi2[2 * i + 0] = __halves2bfloat162(hx, hy);
        hi2[2 * i + 1] = __halves2bfloat162(hz, hw);
        lo2[2 * i + 0] = __halves2bfloat162(
            __float2bfloat16(v.x - __bfloat162float(hx)),
            __float2bfloat16(v.y - __bfloat162float(hy)));
        lo2[2 * i + 1] = __halves2bfloat162(
            __float2bfloat16(v.z - __bfloat162float(hz)),
            __float2bfloat16(v.w - __bfloat162float(hw)));
    }
}

// Transpose + split: in [R][C] fp32 -> hiT/loT [C][R] bf16
__global__ __launch_bounds__(256) void wsplit_kernel(
    const float* __restrict__ W, bf16* __restrict__ hiT,
    bf16* __restrict__ loT, int R, int C)
{
    __shared__ float t[32][33];
    const int c0 = blockIdx.x * 32, r0 = blockIdx.y * 32;
    const int tx = threadIdx.x & 31, ty = threadIdx.x >> 5;
#pragma unroll
    for (int r = 0; r < 32; r += 8)
        t[ty + r][tx] = W[(size_t)(r0 + ty + r) * C + c0 + tx];
    __syncthreads();
#pragma unroll
    for (int r = 0; r < 32; r += 8) {
        float v = t[tx][ty + r];               // element W[r0+tx][c0+ty+r]
        bf16 h = __float2bfloat16(v);
        size_t o = (size_t)(c0 + ty + r) * R + r0 + tx;
        hiT[o] = h;
        loT[o] = __float2bfloat16(v - __bfloat162float(h));
    }
}

// ---------------------------------------------------------------------------
// mma.sync bf16-split GEMM: C = (Ah+Al)[M,K] * (Bh+Bl)^T
// Output: fp32 C (+bias) if C != null, else bf16 hi/lo split to Chi/Clo.
// Block 128x128, K-chunk 32, 8 warps (warp tile 32x64), cp.async double buffer.
// ---------------------------------------------------------------------------
#define TILE_B   10240                 // 128 rows * 80 B
#define STAGE_B  (4 * TILE_B)
#define TC_SMEM  (2 * STAGE_B)         // 81920

__global__ __launch_bounds__(256) void tc_gemm(
    const bf16* __restrict__ Ah, const bf16* __restrict__ Al,
    const bf16* __restrict__ Bh, const bf16* __restrict__ Bl,
    float* __restrict__ C, const float* __restrict__ bias,
    bf16* __restrict__ Chi, bf16* __restrict__ Clo, int Kn, int Nn)
{
    extern __shared__ char smem[];
    const uint32_t sbase = smem_u32(smem);
    const int tid = threadIdx.x, wid = tid >> 5, lane = tid & 31;
    const int warp_m = wid >> 1, warp_n = wid & 1;
    const int m0 = blockIdx.y * 128, n0 = blockIdx.x * 128;

    float acc[2][8][4];
#pragma unroll
    for (int mt = 0; mt < 2; mt++)
#pragma unroll
        for (int nt = 0; nt < 8; nt++)
#pragma unroll
            for (int q = 0; q < 4; q++) acc[mt][nt][q] = 0.f;

    const uint32_t lofs = ((((lane >> 3) & 1) * 8 + (lane & 7)) * 80u) + ((lane >> 4) * 16u);
    const int ld_row0 = tid >> 2;
    const int ld_col  = tid & 3;

    const int NC = Kn >> 5;
#define LOAD_STAGE(s, k0v) do {                                                   \
        const uint32_t stg = sbase + (uint32_t)(s) * STAGE_B;                     \
        _Pragma("unroll")                                                         \
        for (int i = 0; i < 8; i++) {                                             \
            const int tile = i >> 1;                                              \
            const int row = (i & 1) * 64 + ld_row0;                               \
            const uint32_t dst = stg + tile * TILE_B + row * 80 + ld_col * 16;    \
            const bf16* sp =                                                      \
                (tile == 0 ? Ah : tile == 1 ? Al : tile == 2 ? Bh : Bl);          \
            const int grow = (tile < 2 ? m0 : n0) + row;                          \
            const bf16* src = sp + (size_t)grow * Kn + (k0v) + ld_col * 8;        \
            CP_ASYNC16(dst, src);                                                 \
        }                                                                         \
        CP_COMMIT();                                                              \
    } while (0)

    LOAD_STAGE(0, 0);

    for (int c = 0; c < NC; c++) {
        CP_WAIT0();
        __syncthreads();
        if (c + 1 < NC) LOAD_STAGE((c + 1) & 1, (c + 1) << 5);

        const uint32_t stg = sbase + (uint32_t)(c & 1) * STAGE_B;
        const uint32_t a_base = stg + (warp_m * 32) * 80 + lofs;
        const uint32_t b_base = stg + 2 * TILE_B + (warp_n * 64) * 80 + lofs;

#pragma unroll
        for (int ks = 0; ks < 2; ks++) {
            uint32_t ah[2][4], al[2][4], b[4][4];
#pragma unroll
            for (int mt = 0; mt < 2; mt++) {
                LDMATRIX_X4(ah[mt][0], ah[mt][1], ah[mt][2], ah[mt][3],
                            a_base + mt * (16 * 80) + ks * 32);
                LDMATRIX_X4(al[mt][0], al[mt][1], al[mt][2], al[mt][3],
                            a_base + TILE_B + mt * (16 * 80) + ks * 32);
            }
#pragma unroll
            for (int nq = 0; nq < 4; nq++)
                LDMATRIX_X4(b[nq][0], b[nq][1], b[nq][2], b[nq][3],
                            b_base + nq * (16 * 80) + ks * 32);
#pragma unroll
            for (int mt = 0; mt < 2; mt++)
#pragma unroll
                for (int nt = 0; nt < 8; nt++) {
                    const int nq = nt >> 1, sel = nt & 1;
                    MMA_BF16(acc[mt][nt], ah[mt], b[nq][sel], b[nq][sel + 2]);
                    MMA_BF16(acc[mt][nt], al[mt], b[nq][sel], b[nq][sel + 2]);
                }
#pragma unroll
            for (int nq = 0; nq < 4; nq++)
                LDMATRIX_X4(b[nq][0], b[nq][1], b[nq][2], b[nq][3],
                            b_base + TILE_B + nq * (16 * 80) + ks * 32);
#pragma unroll
            for (int mt = 0; mt < 2; mt++)
#pragma unroll
                for (int nt = 0; nt < 8; nt++) {
                    const int nq = nt >> 1, sel = nt & 1;
                    MMA_BF16(acc[mt][nt], ah[mt], b[nq][sel], b[nq][sel + 2]);
                }
        }
        __syncthreads();
    }
#undef LOAD_STAGE

    const int g = lane >> 2, tig = lane & 3;
#pragma unroll
    for (int mt = 0; mt < 2; mt++) {
        const int row0 = m0 + warp_m * 32 + mt * 16 + g;
#pragma unroll
        for (int nt = 0; nt < 8; nt++) {
            const int col = n0 + warp_n * 64 + nt * 8 + 2 * tig;
            if (C) {
                float bx = 0.f, by = 0.f;
                if (bias) { bx = bias[col]; by = bias[col + 1]; }
                *(float2*)(C + (size_t)row0 * Nn + col) =
                    make_float2(acc[mt][nt][0] + bx, acc[mt][nt][1] + by);
                *(float2*)(C + (size_t)(row0 + 8) * Nn + col) =
                    make_float2(acc[mt][nt][2] + bx, acc[mt][nt][3] + by);
            } else {
                uint32_t hi, lo;
                split2(acc[mt][nt][0], acc[mt][nt][1], hi, lo);
                *(uint32_t*)(Chi + (size_t)row0 * Nn + col) = hi;
                *(uint32_t*)(Clo + (size_t)row0 * Nn + col) = lo;
                split2(acc[mt][nt][2], acc[mt][nt][3], hi, lo);
                *(uint32_t*)(Chi + (size_t)(row0 + 8) * Nn + col) = hi;
                *(uint32_t*)(Clo + (size_t)(row0 + 8) * Nn + col) = lo;
            }
        }
    }
}

// ---------------------------------------------------------------------------
// Low-rank projection on MMA:
//   Cp[kp][d] = sum_t E^T[kp][t] * X[t][h*64+d],  per (bh, z), split output.
// Block: 128 kp rows x 64 d, K-chunk 32 over t, 8 warps (m16 each).
// A = E^T tile [128][32] (pitch 80, non-trans), B = X tile [32][64] (pitch 144, trans)
// grid = (KP/128, BHN, 2)
// ---------------------------------------------------------------------------
#define PAL 10240                       // A tile bytes (128*80)
#define PBH (2 * PAL)                   // B hi offset
#define PBL (PBH + 32 * 144)
#define PSTAGE (PBL + 32 * 144)         // 29696
#define PROJ_SMEM (2 * PSTAGE)          // 59392

__global__ __launch_bounds__(256) void proj_mma(
    const bf16* __restrict__ Eh, const bf16* __restrict__ El,
    const bf16* __restrict__ Kh, const bf16* __restrict__ Kl,
    const bf16* __restrict__ Vh, const bf16* __restrict__ Vl,
    bf16* __restrict__ Kph, bf16* __restrict__ Kpl,
    bf16* __restrict__ Vph, bf16* __restrict__ Vpl)
{
    extern __shared__ char smem[];
    const uint32_t sbase = smem_u32(smem);
    const int tid = threadIdx.x, wid = tid >> 5, lane = tid & 31;
    const int m0k = blockIdx.x * 128;
    const int bh = blockIdx.y, z = blockIdx.z;
    const int b = bh >> 4, h = bh & 15;

    const bf16* Xh = z ? Vh : Kh;
    const bf16* Xl = z ? Vl : Kl;
    bf16* Oh = z ? Vph : Kph;
    bf16* Ol = z ? Vpl : Kpl;
    const size_t eoff = (size_t)z * KP * TT;
    const size_t brow = (size_t)b * TT;
    const int hcol = h * 64;

    float cacc[8][4];
#pragma unroll
    for (int nt = 0; nt < 8; nt++)
#pragma unroll
        for (int q = 0; q < 4; q++) cacc[nt][q] = 0.f;

    const uint32_t lofsA = (lane & 15) * 80u + ((lane >> 4) * 16u);
    const uint32_t lofsB = (lane & 15) * 144u + ((lane >> 4) * 16u);
    const int wm = wid * 16;

#define PROJ_LOAD(s, k0v) do {                                                    \
        const uint32_t stg = sbase + (uint32_t)(s) * PSTAGE;                      \
        _Pragma("unroll")                                                         \
        for (int i = 0; i < 2; i++) {                                             \
            const int idx = tid + i * 256;                                        \
            const int r = idx >> 2, cc = idx & 3;                                 \
            const size_t gof = (size_t)(m0k + r) * TT + (k0v) + cc * 8;           \
            CP_ASYNC16(stg + r * 80 + cc * 16, Eh + eoff + gof);                  \
            CP_ASYNC16(stg + PAL + r * 80 + cc * 16, El + eoff + gof);            \
        }                                                                         \
        {                                                                         \
            const int r = tid >> 3, cc = tid & 7;                                 \
            const size_t gof = (brow + (k0v) + r) * DD + hcol + cc * 8;           \
            CP_ASYNC16(stg + PBH + r * 144 + cc * 16, Xh + gof);                  \
            CP_ASYNC16(stg + PBL + r * 144 + cc * 16, Xl + gof);                  \
        }                                                                         \
        CP_COMMIT();                                                              \
    } while (0)

    PROJ_LOAD(0, 0);
    const int NC = TT >> 5;   // 128 chunks
    for (int c = 0; c < NC; c++) {
        CP_WAIT0();
        __syncthreads();
        if (c + 1 < NC) PROJ_LOAD((c + 1) & 1, (c + 1) << 5);

        const uint32_t stg = sbase + (uint32_t)(c & 1) * PSTAGE;
#pragma unroll
        for (int s = 0; s < 2; s++) {
            uint32_t ah[4], al[4], bh4[4], bl4[4];
            LDMATRIX_X4(ah[0], ah[1], ah[2], ah[3], stg + wm * 80 + lofsA + s * 32);
            LDMATRIX_X4(al[0], al[1], al[2], al[3], stg + PAL + wm * 80 + lofsA + s * 32);
#pragma unroll
            for (int ng = 0; ng < 4; ng++) {
                LDMATRIX_X4_T(bh4[0], bh4[1], bh4[2], bh4[3],
                              stg + PBH + s * (16 * 144) + lofsB + ng * 32);
                MMA_BF16(cacc[2 * ng], ah, bh4[0], bh4[1]);
                MMA_BF16(cacc[2 * ng], al, bh4[0], bh4[1]);
                MMA_BF16(cacc[2 * ng + 1], ah, bh4[2], bh4[3]);
                MMA_BF16(cacc[2 * ng + 1], al, bh4[2], bh4[3]);
                LDMATRIX_X4_T(bl4[0], bl4[1], bl4[2], bl4[3],
                              stg + PBL + s * (16 * 144) + lofsB + ng * 32);
                MMA_BF16(cacc[2 * ng], ah, bl4[0], bl4[1]);
                MMA_BF16(cacc[2 * ng + 1], ah, bl4[2], bl4[3]);
            }
        }
        __syncthreads();
    }
#undef PROJ_LOAD

    const int g = lane >> 2, tig = lane & 3;
    const size_t obase = (size_t)bh * KP * DK;
#pragma unroll
    for (int nt = 0; nt < 8; nt++) {
        const int row0 = m0k + wm + g;
        const int col = nt * 8 + 2 * tig;
        uint32_t hi, lo;
        split2(cacc[nt][0], cacc[nt][1], hi, lo);
        *(uint32_t*)(Oh + obase + (size_t)row0 * DK + col) = hi;
        *(uint32_t*)(Ol + obase + (size_t)row0 * DK + col) = lo;
        split2(cacc[nt][2], cacc[nt][3], hi, lo);
        *(uint32_t*)(Oh + obase + (size_t)(row0 + 8) * DK + col) = hi;
        *(uint32_t*)(Ol + obase + (size_t)(row0 + 8) * DK + col) = lo;
    }
}

// ---------------------------------------------------------------------------
// Fused MMA attention per (bh, 128-row t-tile):
//   S = Q*Kp^T (MMA, split), softmax on fragments, ctx = P*Vp (MMA, split),
//   ctx written as bf16 hi/lo into Ch/Cl (feeds Wo GEMM).
// 8 warps, warp = 16 rows. smem: Q,Kp,Vp hi/lo, pitch 144.
// ---------------------------------------------------------------------------
#define AQH 0
#define AQL (AQH + 128 * 144)
#define AKH (AQL + 128 * 144)
#define AKL (AKH + 256 * 144)
#define AVH (AKL + 256 * 144)
#define AVL (AVH + 256 * 144)
#define ATTN_SMEM (AVL + 256 * 144)     // 184320

__global__ __launch_bounds__(256) void attn_mma(
    const bf16* __restrict__ Qh, const bf16* __restrict__ Ql,
    const bf16* __restrict__ Kph, const bf16* __restrict__ Kpl,
    const bf16* __restrict__ Vph, const bf16* __restrict__ Vpl,
    bf16* __restrict__ Ch, bf16* __restrict__ Cl)
{
    extern __shared__ char smem[];
    const uint32_t sbase = smem_u32(smem);
    const int tid = threadIdx.x, wid = tid >> 5, lane = tid & 31;
    const int bh = blockIdx.y, b = bh >> 4, h = bh & 15;
    const int t0 = blockIdx.x * 128;

    // --- loads ---
    const size_t qbase = (size_t)(b * TT + t0) * DD + h * 64;
    for (int idx = tid; idx < 128 * 8; idx += 256) {
        const int r = idx >> 3, c = idx & 7;
        const size_t go = qbase + (size_t)r * DD + c * 8;
        *(uint4*)(smem + AQH + r * 144 + c * 16) = *(const uint4*)(Qh + go);
        *(uint4*)(smem + AQL + r * 144 + c * 16) = *(const uint4*)(Ql + go);
    }
    const size_t kpb = (size_t)bh * KP * DK;
    for (int idx = tid; idx < 256 * 8; idx += 256) {
        const int r = idx >> 3, c = idx & 7;
        const size_t go = kpb + (size_t)r * DK + c * 8;
        *(uint4*)(smem + AKH + r * 144 + c * 16) = *(const uint4*)(Kph + go);
        *(uint4*)(smem + AKL + r * 144 + c * 16) = *(const uint4*)(Kpl + go);
        *(uint4*)(smem + AVH + r * 144 + c * 16) = *(const uint4*)(Vph + go);
        *(uint4*)(smem + AVL + r * 144 + c * 16) = *(const uint4*)(Vpl + go);
    }
    __syncthreads();

    const int wm = wid * 16;
    const uint32_t lofs = (lane & 15) * 144u + ((lane >> 4) * 16u);

    // --- scores: S[16 x 256] per warp ---
    float sacc[32][4];
#pragma unroll
    for (int j = 0; j < 32; j++)
#pragma unroll
        for (int q = 0; q < 4; q++) sacc[j][q] = 0.f;

#pragma unroll
    for (int s = 0; s < 4; s++) {           // k16 over d=64
        uint32_t qh4[4], ql4[4], b4[4];
        LDMATRIX_X4(qh4[0], qh4[1], qh4[2], qh4[3], sbase + AQH + wm * 144 + lofs + s * 32);
        LDMATRIX_X4(ql4[0], ql4[1], ql4[2], ql4[3], sbase + AQL + wm * 144 + lofs + s * 32);
#pragma unroll
        for (int ng = 0; ng < 16; ng++) {   // n16 groups over kp=256
            LDMATRIX_X4(b4[0], b4[1], b4[2], b4[3],
                        sbase + AKH + ng * (16 * 144) + lofs + s * 32);
            MMA_BF16(sacc[2 * ng], qh4, b4[0], b4[2]);
            MMA_BF16(sacc[2 * ng], ql4, b4[0], b4[2]);
            MMA_BF16(sacc[2 * ng + 1], qh4, b4[1], b4[3]);
            MMA_BF16(sacc[2 * ng + 1], ql4, b4[1], b4[3]);
            LDMATRIX_X4(b4[0], b4[1], b4[2], b4[3],
                        sbase + AKL + ng * (16 * 144) + lofs + s * 32);
            MMA_BF16(sacc[2 * ng], qh4, b4[0], b4[2]);
            MMA_BF16(sacc[2 * ng + 1], qh4, b4[1], b4[3]);
        }
    }

    // --- softmax on fragments (rows g and g+8), deferred normalization ---
    float m0 = -1e30f, m1 = -1e30f;
#pragma unroll
    for (int j = 0; j < 32; j++) {
        m0 = fmaxf(m0, fmaxf(sacc[j][0], sacc[j][1]));
        m1 = fmaxf(m1, fmaxf(sacc[j][2], sacc[j][3]));
    }
    m0 = fmaxf(m0, __shfl_xor_sync(0xffffffffu, m0, 1));
    m0 = fmaxf(m0, __shfl_xor_sync(0xffffffffu, m0, 2));
    m1 = fmaxf(m1, __shfl_xor_sync(0xffffffffu, m1, 1));
    m1 = fmaxf(m1, __shfl_xor_sync(0xffffffffu, m1, 2));

    float sum0 = 0.f, sum1 = 0.f;
#pragma unroll
    for (int j = 0; j < 32; j++) {
        float e0 = __expf((sacc[j][0] - m0) * 0.125f);
        float e1 = __expf((sacc[j][1] - m0) * 0.125f);
        float e2 = __expf((sacc[j][2] - m1) * 0.125f);
        float e3 = __expf((sacc[j][3] - m1) * 0.125f);
        sacc[j][0] = e0; sacc[j][1] = e1; sacc[j][2] = e2; sacc[j][3] = e3;
        sum0 += e0 + e1; sum1 += e2 + e3;
    }
    sum0 += __shfl_xor_sync(0xffffffffu, sum0, 1);
    sum0 += __shfl_xor_sync(0xffffffffu, sum0, 2);
    sum1 += __shfl_xor_sync(0xffffffffu, sum1, 1);
    sum1 += __shfl_xor_sync(0xffffffffu, sum1, 2);
    const float inv0 = __frcp_rn(sum0), inv1 = __frcp_rn(sum1);

    // --- ctx = P * Vp, P fragments built in-register from sacc ---
    float cacc[8][4];
#pragma unroll
    for (int nt = 0; nt < 8; nt++)
#pragma unroll
        for (int q = 0; q < 4; q++) cacc[nt][q] = 0.f;

#pragma unroll
    for (int s = 0; s < 16; s++) {          // k16 over kp=256
        uint32_t ah4[4], al4[4], b4[4];
        split2(sacc[2 * s][0],     sacc[2 * s][1],     ah4[0], al4[0]);
        split2(sacc[2 * s][2],     sacc[2 * s][3],     ah4[1], al4[1]);
        split2(sacc[2 * s + 1][0], sacc[2 * s + 1][1], ah4[2], al4[2]);
        split2(sacc[2 * s + 1][2], sacc[2 * s + 1][3], ah4[3], al4[3]);
#pragma unroll
        for (int ng = 0; ng < 4; ng++) {    // n16 groups over d=64
            LDMATRIX_X4_T(b4[0], b4[1], b4[2], b4[3],
                          sbase + AVH + s * (16 * 144) + lofs + ng * 32);
            MMA_BF16(cacc[2 * ng], ah4, b4[0], b4[1]);
            MMA_BF16(cacc[2 * ng], al4, b4[0], b4[1]);
            MMA_BF16(cacc[2 * ng + 1], ah4, b4[2], b4[3]);
            MMA_BF16(cacc[2 * ng + 1], al4, b4[2], b4[3]);
            LDMATRIX_X4_T(b4[0], b4[1], b4[2], b4[3],
                          sbase + AVL + s * (16 * 144) + lofs + ng * 32);
            MMA_BF16(cacc[2 * ng], ah4, b4[0], b4[1]);
            MMA_BF16(cacc[2 * ng + 1], ah4, b4[2], b4[3]);
        }
    }

    // --- epilogue: normalize + split-write ctx ---
    const int g = lane >> 2, tig = lane & 3;
    const size_t r0 = (size_t)(b * TT + t0 + wm + g) * DD + h * 64;
    const size_t r1 = r0 + 8 * DD;
#pragma unroll
    for (int nt = 0; nt < 8; nt++) {
        const int col = nt * 8 + 2 * tig;
        uint32_t hi, lo;
        split2(cacc[nt][0] * inv0, cacc[nt][1] * inv0, hi, lo);
        *(uint32_t*)(Ch + r0 + col) = hi;
        *(uint32_t*)(Cl + r0 + col) = lo;
        split2(cacc[nt][2] * inv1, cacc[nt][3] * inv1, hi, lo);
        *(uint32_t*)(Ch + r1 + col) = hi;
        *(uint32_t*)(Cl + r1 + col) = lo;
    }
}

// ---------------------------------------------------------------------------
// Launch
// ---------------------------------------------------------------------------
extern "C" void kernel_launch(void* const* d_in, const int* in_sizes, int n_in,
                              void* d_out, int out_size)
{
    const float* x  = (const float*)d_in[0];
    const float* Wq = (const float*)d_in[1];
    const float* Wk = (const float*)d_in[2];
    const float* Wv = (const float*)d_in[3];
    const float* Ek = (const float*)d_in[4];
    const float* Ev = (const float*)d_in[5];
    const float* Wo = (const float*)d_in[6];
    const float* bo = (const float*)d_in[7];
    float* out = (float*)d_out;

    bf16 *Ahp, *Alp, *Qhp, *Qlp, *Khp, *Klp, *Vhp, *Vlp, *Whp, *Wlp;
    bf16 *Ethp, *Etlp, *Kphp, *Kplp, *Vphp, *Vplp;
    cudaGetSymbolAddress((void**)&Ahp, g_Ah);
    cudaGetSymbolAddress((void**)&Alp, g_Al);
    cudaGetSymbolAddress((void**)&Qhp, g_Qh);
    cudaGetSymbolAddress((void**)&Qlp, g_Ql);
    cudaGetSymbolAddress((void**)&Khp, g_Kh);
    cudaGetSymbolAddress((void**)&Klp, g_Kl);
    cudaGetSymbolAddress((void**)&Vhp, g_Vh);
    cudaGetSymbolAddress((void**)&Vlp, g_Vl);
    cudaGetSymbolAddress((void**)&Whp, g_Wh);
    cudaGetSymbolAddress((void**)&Wlp, g_Wl);
    cudaGetSymbolAddress((void**)&Ethp, g_Eth);
    cudaGetSymbolAddress((void**)&Etlp, g_Etl);
    cudaGetSymbolAddress((void**)&Kphp, g_Kph);
    cudaGetSymbolAddress((void**)&Kplp, g_Kpl);
    cudaGetSymbolAddress((void**)&Vphp, g_Vph);
    cudaGetSymbolAddress((void**)&Vplp, g_Vpl);

    const size_t WSZ = (size_t)DD * DD;
    bf16* Wqh = Whp + 0 * WSZ; bf16* Wql = Wlp + 0 * WSZ;
    bf16* Wkh = Whp + 1 * WSZ; bf16* Wkl = Wlp + 1 * WSZ;
    bf16* Wvh = Whp + 2 * WSZ; bf16* Wvl = Wlp + 2 * WSZ;
    bf16* Woh = Whp + 3 * WSZ; bf16* Wol = Wlp + 3 * WSZ;

    cudaFuncSetAttribute(tc_gemm, cudaFuncAttributeMaxDynamicSharedMemorySize, TC_SMEM);
    cudaFuncSetAttribute(proj_mma, cudaFuncAttributeMaxDynamicSharedMemorySize, PROJ_SMEM);
    cudaFuncSetAttribute(attn_mma, cudaFuncAttributeMaxDynamicSharedMemorySize, ATTN_SMEM);

    // 1) split x
    split_kernel<<<2048, 256>>>(x, Ahp, Alp, MROWS * DD / 4);
    // 2) transpose+split weights and E
    wsplit_kernel<<<dim3(DD / 32, DD / 32), 256>>>(Wq, Wqh, Wql, DD, DD);
    wsplit_kernel<<<dim3(DD / 32, DD / 32), 256>>>(Wk, Wkh, Wkl, DD, DD);
    wsplit_kernel<<<dim3(DD / 32, DD / 32), 256>>>(Wv, Wvh, Wvl, DD, DD);
    wsplit_kernel<<<dim3(DD / 32, DD / 32), 256>>>(Wo, Woh, Wol, DD, DD);
    wsplit_kernel<<<dim3(KP / 32, TT / 32), 256>>>(Ek, Ethp, Etlp, TT, KP);
    wsplit_kernel<<<dim3(KP / 32, TT / 32), 256>>>(Ev, Ethp + (size_t)KP * TT,
                                                   Etlp + (size_t)KP * TT, TT, KP);

    // 3) QKV projections -> bf16 split outputs
    dim3 ggrid(DD / 128, MROWS / 128);
    tc_gemm<<<ggrid, 256, TC_SMEM>>>(Ahp, Alp, Wqh, Wql, nullptr, nullptr, Qhp, Qlp, DD, DD);
    tc_gemm<<<ggrid, 256, TC_SMEM>>>(Ahp, Alp, Wkh, Wkl, nullptr, nullptr, Khp, Klp, DD, DD);
    tc_gemm<<<ggrid, 256, TC_SMEM>>>(Ahp, Alp, Wvh, Wvl, nullptr, nullptr, Vhp, Vlp, DD, DD);

    // 4) low-rank projections (MMA)
    proj_mma<<<dim3(KP / 128, BHN, 2), 256, PROJ_SMEM>>>(
        Ethp, Etlp, Khp, Klp, Vhp, Vlp, Kphp, Kplp, Vphp, Vplp);

    // 5) fused attention (MMA) -> ctx split into Ah/Al
    attn_mma<<<dim3(TT / 128, BHN), 256, ATTN_SMEM>>>(
        Qhp, Qlp, Kphp, Kplp, Vphp, Vplp, Ahp, Alp);

    // 6) output projection + bias (fp32 out)
    tc_gemm<<<ggrid, 256, TC_SMEM>>>(Ahp, Alp, Woh, Wol, out, bo, nullptr, nullptr, DD, DD);
}

// round 5
// speedup vs baseline: 3.4472x; 1.5453x over previous
#include <cuda_runtime.h>
#include <cuda_fp16.h>
#include <cstdint>
#include <math.h>

// Problem constants
#define BB 4
#define TT 4096
#define DD 1024
#define HH 16
#define KP 256
#define DK 64
#define MROWS (BB*TT)          // 16384
#define BHN (BB*HH)            // 64

typedef __half half_t;

// ---------------------------------------------------------------------------
// Scratch (static device globals; no allocation allowed)
// ---------------------------------------------------------------------------
__device__ half_t g_Ah[(size_t)MROWS * DD];      // x split hi (later ctx hi)
__device__ half_t g_Al[(size_t)MROWS * DD];      // x split lo (later ctx lo)
__device__ half_t g_Qh[(size_t)MROWS * DD];
__device__ half_t g_Ql[(size_t)MROWS * DD];
__device__ half_t g_K [(size_t)MROWS * DD];      // plain
__device__ half_t g_V [(size_t)MROWS * DD];      // plain
__device__ half_t g_Wt[4][(size_t)DD * DD];      // transposed [N][K], plain
__device__ half_t g_Eth[(size_t)2 * KP * TT];    // E^T split hi [z][kp][t]
__device__ half_t g_Etl[(size_t)2 * KP * TT];    // E^T split lo
__device__ half_t g_Kp[(size_t)BHN * KP * DK];   // plain
__device__ half_t g_Vp[(size_t)BHN * KP * DK];   // plain

// ---------------------------------------------------------------------------
// Helpers
// ---------------------------------------------------------------------------
__device__ __forceinline__ uint32_t smem_u32(const void* p) {
    uint32_t a;
    asm("{ .reg .u64 t; cvta.to.shared.u64 t, %1; cvt.u32.u64 %0, t; }" : "=r"(a) : "l"(p));
    return a;
}

#define CP_ASYNC16(dst, src) \
    asm volatile("cp.async.cg.shared.global [%0], [%1], 16;" :: "r"(dst), "l"(src))
#define CP_COMMIT() asm volatile("cp.async.commit_group;")
#define CP_WAIT0()  asm volatile("cp.async.wait_group 0;" ::: "memory")

#define LDMATRIX_X4(r0, r1, r2, r3, addr) \
    asm volatile("ldmatrix.sync.aligned.m8n8.x4.shared.b16 {%0,%1,%2,%3}, [%4];" \
        : "=r"(r0), "=r"(r1), "=r"(r2), "=r"(r3) : "r"(addr))
#define LDMATRIX_X4_T(r0, r1, r2, r3, addr) \
    asm volatile("ldmatrix.sync.aligned.m8n8.x4.trans.shared.b16 {%0,%1,%2,%3}, [%4];" \
        : "=r"(r0), "=r"(r1), "=r"(r2), "=r"(r3) : "r"(addr))

#define MMA_F16(d, a, b0_, b1_) \
    asm volatile("mma.sync.aligned.m16n8k16.row.col.f32.f16.f16.f32 " \
        "{%0,%1,%2,%3},{%4,%5,%6,%7},{%8,%9},{%0,%1,%2,%3};" \
        : "+f"((d)[0]), "+f"((d)[1]), "+f"((d)[2]), "+f"((d)[3]) \
        : "r"((a)[0]), "r"((a)[1]), "r"((a)[2]), "r"((a)[3]), "r"(b0_), "r"(b1_))

__device__ __forceinline__ uint32_t pack_h2(float a, float b) {
    __half2 t = __floats2half2_rn(a, b);
    return *(uint32_t*)&t;
}
__device__ __forceinline__ void split2h(float a, float b, uint32_t& hi, uint32_t& lo) {
    __half2 h = __floats2half2_rn(a, b);
    hi = *(uint32_t*)&h;
    lo = pack_h2(a - __low2float(h), b - __high2float(h));
}

// ---------------------------------------------------------------------------
// Split fp32 -> fp16 hi/lo (vectorized x4)
// ---------------------------------------------------------------------------
__global__ __launch_bounds__(256) void split_kernel(
    const float* __restrict__ src, half_t* __restrict__ hi,
    half_t* __restrict__ lo, int n4)
{
    uint32_t* hi2 = (uint32_t*)hi;
    uint32_t* lo2 = (uint32_t*)lo;
    int stride = gridDim.x * blockDim.x;
    for (int i = blockIdx.x * blockDim.x + threadIdx.x; i < n4; i += stride) {
        float4 v = ((const float4*)src)[i];
        uint32_t h0, l0, h1, l1;
        split2h(v.x, v.y, h0, l0);
        split2h(v.z, v.w, h1, l1);
        hi2[2 * i + 0] = h0; hi2[2 * i + 1] = h1;
        lo2[2 * i + 0] = l0; lo2[2 * i + 1] = l1;
    }
}

// Transpose + convert: in [R][C] fp32 -> out [C][R] fp16 plain
__global__ __launch_bounds__(256) void wconv_kernel(
    const float* __restrict__ W, half_t* __restrict__ Wt, int R, int C)
{
    __shared__ float t[32][33];
    const int c0 = blockIdx.x * 32, r0 = blockIdx.y * 32;
    const int tx = threadIdx.x & 31, ty = threadIdx.x >> 5;
#pragma unroll
    for (int r = 0; r < 32; r += 8)
        t[ty + r][tx] = W[(size_t)(r0 + ty + r) * C + c0 + tx];
    __syncthreads();
#pragma unroll
    for (int r = 0; r < 32; r += 8)
        Wt[(size_t)(c0 + ty + r) * R + r0 + tx] = __float2half(t[tx][ty + r]);
}

// Transpose + split: in [R][C] fp32 -> hiT/loT [C][R] fp16
__global__ __launch_bounds__(256) void wsplit_kernel(
    const float* __restrict__ W, half_t* __restrict__ hiT,
    half_t* __restrict__ loT, int R, int C)
{
    __shared__ float t[32][33];
    const int c0 = blockIdx.x * 32, r0 = blockIdx.y * 32;
    const int tx = threadIdx.x & 31, ty = threadIdx.x >> 5;
#pragma unroll
    for (int r = 0; r < 32; r += 8)
        t[ty + r][tx] = W[(size_t)(r0 + ty + r) * C + c0 + tx];
    __syncthreads();
#pragma unroll
    for (int r = 0; r < 32; r += 8) {
        float v = t[tx][ty + r];
        half_t h = __float2half(v);
        size_t o = (size_t)(c0 + ty + r) * R + r0 + tx;
        hiT[o] = h;
        loT[o] = __float2half(v - __half2float(h));
    }
}

// ---------------------------------------------------------------------------
// mma.sync fp16 split-A GEMM: C = (Ah+Al)[M,K] * Bt[N,K]^T
//   acc += Ah*B + Al*B   (2 MMAs per tile)
// Two output modes:
//   C != null : fp32 write (+bias), Nn = 1024 columns
//   C == null : QKV routing — global col block selects Q(split)/K(plain)/V(plain)
// Block 128x128, K-chunk 32, 8 warps (warp tile 32x64), cp.async double buffer.
// ---------------------------------------------------------------------------
#define TILE_B   10240                 // 128 rows * 80 B
#define STAGE_B  (3 * TILE_B)          // AH, AL, B
#define TC_SMEM  (2 * STAGE_B)         // 61440

__global__ __launch_bounds__(256) void tc_gemm(
    const half_t* __restrict__ Ah, const half_t* __restrict__ Al,
    const half_t* __restrict__ Bt,
    float* __restrict__ C, const float* __restrict__ bias,
    half_t* __restrict__ Qh, half_t* __restrict__ Ql,
    half_t* __restrict__ Ko, half_t* __restrict__ Vo, int Kn)
{
    extern __shared__ char smem[];
    const uint32_t sbase = smem_u32(smem);
    const int tid = threadIdx.x, wid = tid >> 5, lane = tid & 31;
    const int warp_m = wid >> 1, warp_n = wid & 1;
    const int m0 = blockIdx.y * 128;
    const int n0g = blockIdx.x * 128;   // global col (may exceed 1024 in QKV mode)

    float acc[2][8][4];
#pragma unroll
    for (int mt = 0; mt < 2; mt++)
#pragma unroll
        for (int nt = 0; nt < 8; nt++)
#pragma unroll
            for (int q = 0; q < 4; q++) acc[mt][nt][q] = 0.f;

    const uint32_t lofs = ((((lane >> 3) & 1) * 8 + (lane & 7)) * 80u) + ((lane >> 4) * 16u);
    const int ld_row0 = tid >> 2;        // 0..63
    const int ld_col  = tid & 3;

    const int NC = Kn >> 5;
#define LOAD_STAGE(s, k0v) do {                                                   \
        const uint32_t stg = sbase + (uint32_t)(s) * STAGE_B;                     \
        _Pragma("unroll")                                                         \
        for (int i = 0; i < 6; i++) {                                             \
            const int tile = i >> 1;                                              \
            const int row = (i & 1) * 64 + ld_row0;                               \
            const uint32_t dst = stg + tile * TILE_B + row * 80 + ld_col * 16;    \
            const half_t* sp = (tile == 0 ? Ah : tile == 1 ? Al : Bt);            \
            const int grow = (tile < 2 ? m0 : n0g) + row;                         \
            const half_t* src = sp + (size_t)grow * Kn + (k0v) + ld_col * 8;      \
            CP_ASYNC16(dst, src);                                                 \
        }                                                                         \
        CP_COMMIT();                                                              \
    } while (0)

    LOAD_STAGE(0, 0);

    for (int c = 0; c < NC; c++) {
        CP_WAIT0();
        __syncthreads();
        if (c + 1 < NC) LOAD_STAGE((c + 1) & 1, (c + 1) << 5);

        const uint32_t stg = sbase + (uint32_t)(c & 1) * STAGE_B;
        const uint32_t a_base = stg + (warp_m * 32) * 80 + lofs;
        const uint32_t b_base = stg + 2 * TILE_B + (warp_n * 64) * 80 + lofs;

#pragma unroll
        for (int ks = 0; ks < 2; ks++) {
            uint32_t ah[2][4], al[2][4], b[4][4];
#pragma unroll
            for (int mt = 0; mt < 2; mt++) {
                LDMATRIX_X4(ah[mt][0], ah[mt][1], ah[mt][2], ah[mt][3],
                            a_base + mt * (16 * 80) + ks * 32);
                LDMATRIX_X4(al[mt][0], al[mt][1], al[mt][2], al[mt][3],
                            a_base + TILE_B + mt * (16 * 80) + ks * 32);
            }
#pragma unroll
            for (int nq = 0; nq < 4; nq++)
                LDMATRIX_X4(b[nq][0], b[nq][1], b[nq][2], b[nq][3],
                            b_base + nq * (16 * 80) + ks * 32);
#pragma unroll
            for (int mt = 0; mt < 2; mt++)
#pragma unroll
                for (int nt = 0; nt < 8; nt++) {
                    const int nq = nt >> 1, sel = nt & 1;
                    MMA_F16(acc[mt][nt], ah[mt], b[nq][sel], b[nq][sel + 2]);
                    MMA_F16(acc[mt][nt], al[mt], b[nq][sel], b[nq][sel + 2]);
                }
        }
        __syncthreads();
    }
#undef LOAD_STAGE

    const int g = lane >> 2, tig = lane & 3;
#pragma unroll
    for (int mt = 0; mt < 2; mt++) {
        const int row0 = m0 + warp_m * 32 + mt * 16 + g;
#pragma unroll
        for (int nt = 0; nt < 8; nt++) {
            const int colg = n0g + warp_n * 64 + nt * 8 + 2 * tig;
            if (C) {
                float bx = 0.f, by = 0.f;
                if (bias) { bx = bias[colg]; by = bias[colg + 1]; }
                *(float2*)(C + (size_t)row0 * DD + colg) =
                    make_float2(acc[mt][nt][0] + bx, acc[mt][nt][1] + by);
                *(float2*)(C + (size_t)(row0 + 8) * DD + colg) =
                    make_float2(acc[mt][nt][2] + bx, acc[mt][nt][3] + by);
            } else {
                const int which = colg >> 10;
                const int col = colg & 1023;
                const size_t o0 = (size_t)row0 * DD + col;
                const size_t o1 = (size_t)(row0 + 8) * DD + col;
                if (which == 0) {
                    uint32_t hi, lo;
                    split2h(acc[mt][nt][0], acc[mt][nt][1], hi, lo);
                    *(uint32_t*)(Qh + o0) = hi; *(uint32_t*)(Ql + o0) = lo;
                    split2h(acc[mt][nt][2], acc[mt][nt][3], hi, lo);
                    *(uint32_t*)(Qh + o1) = hi; *(uint32_t*)(Ql + o1) = lo;
                } else {
                    half_t* O = (which == 1) ? Ko : Vo;
                    *(uint32_t*)(O + o0) = pack_h2(acc[mt][nt][0], acc[mt][nt][1]);
                    *(uint32_t*)(O + o1) = pack_h2(acc[mt][nt][2], acc[mt][nt][3]);
                }
            }
        }
    }
}

// ---------------------------------------------------------------------------
// Low-rank projection on MMA:
//   Cp[kp][d] = sum_t (Eh+El)^T[kp][t] * X[t][h*64+d],  per (bh, z), plain out.
// A = E^T hi/lo [128][32] (pitch 80), B = X tile [32][64] (pitch 144, trans)
// grid = (KP/128, BHN, 2)
// ---------------------------------------------------------------------------
#define PAL 10240                       // 128*80
#define PB  (2 * PAL)                   // B offset
#define PSTAGE (PB + 32 * 144)          // 25088
#define PROJ_SMEM (2 * PSTAGE)          // 50176

__global__ __launch_bounds__(256) void proj_mma(
    const half_t* __restrict__ Eh, const half_t* __restrict__ El,
    const half_t* __restrict__ Kb, const half_t* __restrict__ Vb,
    half_t* __restrict__ Kp, half_t* __restrict__ Vp)
{
    extern __shared__ char smem[];
    const uint32_t sbase = smem_u32(smem);
    const int tid = threadIdx.x, wid = tid >> 5, lane = tid & 31;
    const int m0k = blockIdx.x * 128;
    const int bh = blockIdx.y, z = blockIdx.z;
    const int b = bh >> 4, h = bh & 15;

    const half_t* X = z ? Vb : Kb;
    half_t* O = z ? Vp : Kp;
    const size_t eoff = (size_t)z * KP * TT;
    const size_t brow = (size_t)b * TT;
    const int hcol = h * 64;

    float cacc[8][4];
#pragma unroll
    for (int nt = 0; nt < 8; nt++)
#pragma unroll
        for (int q = 0; q < 4; q++) cacc[nt][q] = 0.f;

    const uint32_t lofsA = (lane & 15) * 80u + ((lane >> 4) * 16u);
    const uint32_t lofsB = (lane & 15) * 144u + ((lane >> 4) * 16u);
    const int wm = wid * 16;

#define PROJ_LOAD(s, k0v) do {                                                    \
        const uint32_t stg = sbase + (uint32_t)(s) * PSTAGE;                      \
        _Pragma("unroll")                                                         \
        for (int i = 0; i < 2; i++) {                                             \
            const int idx = tid + i * 256;                                        \
            const int r = idx >> 2, cc = idx & 3;                                 \
            const size_t gof = (size_t)(m0k + r) * TT + (k0v) + cc * 8;           \
            CP_ASYNC16(stg + r * 80 + cc * 16, Eh + eoff + gof);                  \
            CP_ASYNC16(stg + PAL + r * 80 + cc * 16, El + eoff + gof);            \
        }                                                                         \
        {                                                                         \
            const int r = tid >> 3, cc = tid & 7;                                 \
            const size_t gof = (brow + (k0v) + r) * DD + hcol + cc * 8;           \
            CP_ASYNC16(stg + PB + r * 144 + cc * 16, X + gof);                    \
        }                                                                         \
        CP_COMMIT();                                                              \
    } while (0)

    PROJ_LOAD(0, 0);
    const int NC = TT >> 5;
    for (int c = 0; c < NC; c++) {
        CP_WAIT0();
        __syncthreads();
        if (c + 1 < NC) PROJ_LOAD((c + 1) & 1, (c + 1) << 5);

        const uint32_t stg = sbase + (uint32_t)(c & 1) * PSTAGE;
#pragma unroll
        for (int s = 0; s < 2; s++) {
            uint32_t ah[4], al[4], b4[4];
            LDMATRIX_X4(ah[0], ah[1], ah[2], ah[3], stg + wm * 80 + lofsA + s * 32);
            LDMATRIX_X4(al[0], al[1], al[2], al[3], stg + PAL + wm * 80 + lofsA + s * 32);
#pragma unroll
            for (int ng = 0; ng < 4; ng++) {
                LDMATRIX_X4_T(b4[0], b4[1], b4[2], b4[3],
                              stg + PB + s * (16 * 144) + lofsB + ng * 32);
                MMA_F16(cacc[2 * ng], ah, b4[0], b4[1]);
                MMA_F16(cacc[2 * ng], al, b4[0], b4[1]);
                MMA_F16(cacc[2 * ng + 1], ah, b4[2], b4[3]);
                MMA_F16(cacc[2 * ng + 1], al, b4[2], b4[3]);
            }
        }
        __syncthreads();
    }
#undef PROJ_LOAD

    const int g = lane >> 2, tig = lane & 3;
    const size_t obase = (size_t)bh * KP * DK;
#pragma unroll
    for (int nt = 0; nt < 8; nt++) {
        const int row0 = m0k + wm + g;
        const int col = nt * 8 + 2 * tig;
        *(uint32_t*)(O + obase + (size_t)row0 * DK + col) =
            pack_h2(cacc[nt][0], cacc[nt][1]);
        *(uint32_t*)(O + obase + (size_t)(row0 + 8) * DK + col) =
            pack_h2(cacc[nt][2], cacc[nt][3]);
    }
}

// ---------------------------------------------------------------------------
// Fused MMA attention per (bh, 128-row t-tile):
//   S = (Qh+Ql)*Kp^T, softmax on fragments, ctx = (Ph+Pl)*Vp,
//   ctx written as fp16 hi/lo into Ch/Cl (feeds Wo GEMM).
// ---------------------------------------------------------------------------
#define AQH 0
#define AQL (AQH + 128 * 144)
#define AK  (AQL + 128 * 144)
#define AV  (AK  + 256 * 144)
#define ATTN_SMEM (AV + 256 * 144)      // 110592

__global__ __launch_bounds__(256) void attn_mma(
    const half_t* __restrict__ Qh, const half_t* __restrict__ Ql,
    const half_t* __restrict__ Kp, const half_t* __restrict__ Vp,
    half_t* __restrict__ Ch, half_t* __restrict__ Cl)
{
    extern __shared__ char smem[];
    const uint32_t sbase = smem_u32(smem);
    const int tid = threadIdx.x, wid = tid >> 5, lane = tid & 31;
    const int bh = blockIdx.y, b = bh >> 4, h = bh & 15;
    const int t0 = blockIdx.x * 128;

    const size_t qbase = (size_t)(b * TT + t0) * DD + h * 64;
    for (int idx = tid; idx < 128 * 8; idx += 256) {
        const int r = idx >> 3, c = idx & 7;
        const size_t go = qbase + (size_t)r * DD + c * 8;
        *(uint4*)(smem + AQH + r * 144 + c * 16) = *(const uint4*)(Qh + go);
        *(uint4*)(smem + AQL + r * 144 + c * 16) = *(const uint4*)(Ql + go);
    }
    const size_t kpb = (size_t)bh * KP * DK;
    for (int idx = tid; idx < 256 * 8; idx += 256) {
        const int r = idx >> 3, c = idx & 7;
        const size_t go = kpb + (size_t)r * DK + c * 8;
        *(uint4*)(smem + AK + r * 144 + c * 16) = *(const uint4*)(Kp + go);
        *(uint4*)(smem + AV + r * 144 + c * 16) = *(const uint4*)(Vp + go);
    }
    __syncthreads();

    const int wm = wid * 16;
    const uint32_t lofs = (lane & 15) * 144u + ((lane >> 4) * 16u);

    // --- scores: S[16 x 256] per warp ---
    float sacc[32][4];
#pragma unroll
    for (int j = 0; j < 32; j++)
#pragma unroll
        for (int q = 0; q < 4; q++) sacc[j][q] = 0.f;

#pragma unroll
    for (int s = 0; s < 4; s++) {
        uint32_t qh4[4], ql4[4], b4[4];
        LDMATRIX_X4(qh4[0], qh4[1], qh4[2], qh4[3], sbase + AQH + wm * 144 + lofs + s * 32);
        LDMATRIX_X4(ql4[0], ql4[1], ql4[2], ql4[3], sbase + AQL + wm * 144 + lofs + s * 32);
#pragma unroll
        for (int ng = 0; ng < 16; ng++) {
            LDMATRIX_X4(b4[0], b4[1], b4[2], b4[3],
                        sbase + AK + ng * (16 * 144) + lofs + s * 32);
            MMA_F16(sacc[2 * ng], qh4, b4[0], b4[2]);
            MMA_F16(sacc[2 * ng], ql4, b4[0], b4[2]);
            MMA_F16(sacc[2 * ng + 1], qh4, b4[1], b4[3]);
            MMA_F16(sacc[2 * ng + 1], ql4, b4[1], b4[3]);
        }
    }

    // --- softmax on fragments ---
    float m0 = -1e30f, m1 = -1e30f;
#pragma unroll
    for (int j = 0; j < 32; j++) {
        m0 = fmaxf(m0, fmaxf(sacc[j][0], sacc[j][1]));
        m1 = fmaxf(m1, fmaxf(sacc[j][2], sacc[j][3]));
    }
    m0 = fmaxf(m0, __shfl_xor_sync(0xffffffffu, m0, 1));
    m0 = fmaxf(m0, __shfl_xor_sync(0xffffffffu, m0, 2));
    m1 = fmaxf(m1, __shfl_xor_sync(0xffffffffu, m1, 1));
    m1 = fmaxf(m1, __shfl_xor_sync(0xffffffffu, m1, 2));

    float sum0 = 0.f, sum1 = 0.f;
#pragma unroll
    for (int j = 0; j < 32; j++) {
        float e0 = __expf((sacc[j][0] - m0) * 0.125f);
        float e1 = __expf((sacc[j][1] - m0) * 0.125f);
        float e2 = __expf((sacc[j][2] - m1) * 0.125f);
        float e3 = __expf((sacc[j][3] - m1) * 0.125f);
        sacc[j][0] = e0; sacc[j][1] = e1; sacc[j][2] = e2; sacc[j][3] = e3;
        sum0 += e0 + e1; sum1 += e2 + e3;
    }
    sum0 += __shfl_xor_sync(0xffffffffu, sum0, 1);
    sum0 += __shfl_xor_sync(0xffffffffu, sum0, 2);
    sum1 += __shfl_xor_sync(0xffffffffu, sum1, 1);
    sum1 += __shfl_xor_sync(0xffffffffu, sum1, 2);
    const float inv0 = __frcp_rn(sum0), inv1 = __frcp_rn(sum1);

    // --- ctx = P * Vp, P split in-register ---
    float cacc[8][4];
#pragma unroll
    for (int nt = 0; nt < 8; nt++)
#pragma unroll
        for (int q = 0; q < 4; q++) cacc[nt][q] = 0.f;

#pragma unroll
    for (int s = 0; s < 16; s++) {
        uint32_t ah4[4], al4[4], b4[4];
        split2h(sacc[2 * s][0],     sacc[2 * s][1],     ah4[0], al4[0]);
        split2h(sacc[2 * s][2],     sacc[2 * s][3],     ah4[1], al4[1]);
        split2h(sacc[2 * s + 1][0], sacc[2 * s + 1][1], ah4[2], al4[2]);
        split2h(sacc[2 * s + 1][2], sacc[2 * s + 1][3], ah4[3], al4[3]);
#pragma unroll
        for (int ng = 0; ng < 4; ng++) {
            LDMATRIX_X4_T(b4[0], b4[1], b4[2], b4[3],
                          sbase + AV + s * (16 * 144) + lofs + ng * 32);
            MMA_F16(cacc[2 * ng], ah4, b4[0], b4[1]);
            MMA_F16(cacc[2 * ng], al4, b4[0], b4[1]);
            MMA_F16(cacc[2 * ng + 1], ah4, b4[2], b4[3]);
            MMA_F16(cacc[2 * ng + 1], al4, b4[2], b4[3]);
        }
    }

    // --- epilogue: normalize + split-write ctx ---
    const int g = lane >> 2, tig = lane & 3;
    const size_t r0 = (size_t)(b * TT + t0 + wm + g) * DD + h * 64;
    const size_t r1 = r0 + 8 * DD;
#pragma unroll
    for (int nt = 0; nt < 8; nt++) {
        const int col = nt * 8 + 2 * tig;
        uint32_t hi, lo;
        split2h(cacc[nt][0] * inv0, cacc[nt][1] * inv0, hi, lo);
        *(uint32_t*)(Ch + r0 + col) = hi;
        *(uint32_t*)(Cl + r0 + col) = lo;
        split2h(cacc[nt][2] * inv1, cacc[nt][3] * inv1, hi, lo);
        *(uint32_t*)(Ch + r1 + col) = hi;
        *(uint32_t*)(Cl + r1 + col) = lo;
    }
}

// ---------------------------------------------------------------------------
// Launch
// ---------------------------------------------------------------------------
extern "C" void kernel_launch(void* const* d_in, const int* in_sizes, int n_in,
                              void* d_out, int out_size)
{
    const float* x  = (const float*)d_in[0];
    const float* Wq = (const float*)d_in[1];
    const float* Wk = (const float*)d_in[2];
    const float* Wv = (const float*)d_in[3];
    const float* Ek = (const float*)d_in[4];
    const float* Ev = (const float*)d_in[5];
    const float* Wo = (const float*)d_in[6];
    const float* bo = (const float*)d_in[7];
    float* out = (float*)d_out;

    half_t *Ahp, *Alp, *Qhp, *Qlp, *Kbp, *Vbp, *Wtp, *Ethp, *Etlp, *Kpp, *Vpp;
    cudaGetSymbolAddress((void**)&Ahp, g_Ah);
    cudaGetSymbolAddress((void**)&Alp, g_Al);
    cudaGetSymbolAddress((void**)&Qhp, g_Qh);
    cudaGetSymbolAddress((void**)&Qlp, g_Ql);
    cudaGetSymbolAddress((void**)&Kbp, g_K);
    cudaGetSymbolAddress((void**)&Vbp, g_V);
    cudaGetSymbolAddress((void**)&Wtp, g_Wt);
    cudaGetSymbolAddress((void**)&Ethp, g_Eth);
    cudaGetSymbolAddress((void**)&Etlp, g_Etl);
    cudaGetSymbolAddress((void**)&Kpp, g_Kp);
    cudaGetSymbolAddress((void**)&Vpp, g_Vp);

    const size_t WSZ = (size_t)DD * DD;

    cudaFuncSetAttribute(tc_gemm, cudaFuncAttributeMaxDynamicSharedMemorySize, TC_SMEM);
    cudaFuncSetAttribute(proj_mma, cudaFuncAttributeMaxDynamicSharedMemorySize, PROJ_SMEM);
    cudaFuncSetAttribute(attn_mma, cudaFuncAttributeMaxDynamicSharedMemorySize, ATTN_SMEM);

    // 1) split x -> fp16 hi/lo
    split_kernel<<<2048, 256>>>(x, Ahp, Alp, MROWS * DD / 4);
    // 2) transpose+convert weights (plain); transpose+split E
    dim3 wg(DD / 32, DD / 32);
    wconv_kernel<<<wg, 256>>>(Wq, Wtp + 0 * WSZ, DD, DD);
    wconv_kernel<<<wg, 256>>>(Wk, Wtp + 1 * WSZ, DD, DD);
    wconv_kernel<<<wg, 256>>>(Wv, Wtp + 2 * WSZ, DD, DD);
    wconv_kernel<<<wg, 256>>>(Wo, Wtp + 3 * WSZ, DD, DD);
    wsplit_kernel<<<dim3(KP / 32, TT / 32), 256>>>(Ek, Ethp, Etlp, TT, KP);
    wsplit_kernel<<<dim3(KP / 32, TT / 32), 256>>>(Ev, Ethp + (size_t)KP * TT,
                                                   Etlp + (size_t)KP * TT, TT, KP);

    // 3) fused QKV projection: B = concat(WqT, WkT, WvT) [3072][1024]
    tc_gemm<<<dim3(3 * DD / 128, MROWS / 128), 256, TC_SMEM>>>(
        Ahp, Alp, Wtp, nullptr, nullptr, Qhp, Qlp, Kbp, Vbp, DD);

    // 4) low-rank projections
    proj_mma<<<dim3(KP / 128, BHN, 2), 256, PROJ_SMEM>>>(
        Ethp, Etlp, Kbp, Vbp, Kpp, Vpp);

    // 5) fused attention -> ctx split into Ah/Al
    attn_mma<<<dim3(TT / 128, BHN), 256, ATTN_SMEM>>>(
        Qhp, Qlp, Kpp, Vpp, Ahp, Alp);

    // 6) output projection + bias (fp32 out)
    tc_gemm<<<dim3(DD / 128, MROWS / 128), 256, TC_SMEM>>>(
        Ahp, Alp, Wtp + 3 * WSZ, out, bo, nullptr, nullptr, nullptr, nullptr, DD);
}